// round 1
// baseline (speedup 1.0000x reference)
#include <cuda_runtime.h>
#include <cstdint>

// Who2com reduces exactly to: out = bevs.
//
// Reference tail:
//   attn = softmax(attn, axis=1)
//   feat_fuse = attn.sum(axis=1)[:, :, None, None, None] * bevs
// softmax normalizes over axis 1 and .sum(axis=1) sums over the SAME axis,
// so the scale is exactly 1.0 for every (b, q). The convs / MLPs / attention
// only produce softmax logits, which the sum-after-softmax annihilates.
// => kernel is a pure 84 MB copy of d_in[0] into d_out.

__global__ __launch_bounds__(256) void who2com_copy_kernel(
    const float4* __restrict__ src, float4* __restrict__ dst, int n_vec4)
{
    int stride = gridDim.x * blockDim.x;
    int i = blockIdx.x * blockDim.x + threadIdx.x;
    // Unrolled grid-stride loop: batch independent loads up front (high MLP)
    // so the DRAM pipe stays saturated.
    #pragma unroll 4
    for (; i < n_vec4; i += stride) {
        dst[i] = src[i];
    }
}

extern "C" void kernel_launch(void* const* d_in, const int* in_sizes, int n_in,
                              void* d_out, int out_size)
{
    const float4* src = (const float4*)d_in[0];   // bevs: [1,4,80,256,256] fp32
    float4* dst = (float4*)d_out;

    // out_size = 1*4*80*256*256 = 20,971,520 floats; divisible by 4.
    int n_vec4 = out_size >> 2;  // 5,242,880

    const int threads = 256;
    // ~4 waves on 148 SMs at high occupancy: enough blocks to saturate HBM,
    // few enough to keep launch overhead negligible.
    int blocks = (n_vec4 + threads * 8 - 1) / (threads * 8);  // ~2560 blocks, 8 vec4/thread
    who2com_copy_kernel<<<blocks, threads>>>(src, dst, n_vec4);
}